// round 4
// baseline (speedup 1.0000x reference)
#include <cuda_runtime.h>
#include <cuda_bf16.h>
#include <math.h>

// Problem constants (fixed by the reference)
#define NN 20000
#define EE 640000
#define GG 128
#define H1 128
#define H2 128
#define RR 8
#define KAGG (RR * GG)   // 1024

// ---------------- scratch (device globals; device-code use only) -----------
__device__ float g_cnt[NN * RR];
__device__ float g_agg[(size_t)NN * KAGG]; // ~82MB
__device__ float g_h[NN * H1];
__device__ float g_q[NN * H2];
__device__ float g_k[NN * H2];
__device__ float g_v[NN * H2];
__device__ float g_e[EE];
__device__ float g_den[NN];

// ---------------- fused zero kernel ----------------------------------------
__global__ void zero_kernel() {
    size_t i = ((size_t)blockIdx.x * blockDim.x + threadIdx.x) * 4;
    size_t n = (size_t)NN * KAGG;
    if (i + 3 < n) *(float4*)(&g_agg[i]) = make_float4(0.f, 0.f, 0.f, 0.f);
    size_t j = (size_t)blockIdx.x * blockDim.x + threadIdx.x;
    if (j < NN * RR) g_cnt[j] = 0.f;
    if (j < NN) g_den[j] = 0.f;
}

// ---------------- edge counting --------------------------------------------
__global__ void count_kernel(const int* __restrict__ dst,
                             const int* __restrict__ etype) {
    int e = blockIdx.x * blockDim.x + threadIdx.x;
    if (e >= EE) return;
    atomicAdd(&g_cnt[dst[e] * RR + etype[e]], 1.0f);
}

// ---------------- RGCN scatter: agg[dst, rel] += x[src]/cnt ----------------
__global__ void scatter_rgcn_kernel(const int* __restrict__ src,
                                    const int* __restrict__ dst,
                                    const int* __restrict__ etype,
                                    const float* __restrict__ x) {
    int e = blockIdx.x * 8 + (threadIdx.x >> 5);
    if (e >= EE) return;
    int lane = threadIdx.x & 31;
    int s = src[e], d = dst[e], r = etype[e];
    float inv = 1.0f / fmaxf(g_cnt[d * RR + r], 1.0f);
    float4 xv = *(const float4*)&x[(size_t)s * GG + lane * 4];
    float* ag = g_agg + (size_t)d * KAGG + r * GG + lane * 4;
    atomicAdd(ag + 0, xv.x * inv);
    atomicAdd(ag + 1, xv.y * inv);
    atomicAdd(ag + 2, xv.z * inv);
    atomicAdd(ag + 3, xv.w * inv);
}

// ---------------- 128x128x16 GEMM core --------------------------------------
__device__ __forceinline__ void mm_seg(const float* __restrict__ A, int lda, int K,
                                       const float* __restrict__ B,
                                       float (*As)[128], float (*Bs)[128],
                                       int row0, int M, float acc[8][8]) {
    int tid = threadIdx.x;
    int tx = tid & 15, ty = tid >> 4;
    for (int k0 = 0; k0 < K; k0 += 16) {
        #pragma unroll
        for (int i = 0; i < 2; i++) {
            int idx = tid + i * 256;        // 0..511
            int r = idx >> 2;               // row 0..127
            int kc = (idx & 3) * 4;         // 0,4,8,12
            int gr = row0 + r;
            float4 v = make_float4(0.f, 0.f, 0.f, 0.f);
            if (gr < M) v = *(const float4*)&A[(size_t)gr * lda + k0 + kc];
            As[kc + 0][r] = v.x; As[kc + 1][r] = v.y;
            As[kc + 2][r] = v.z; As[kc + 3][r] = v.w;
        }
        #pragma unroll
        for (int i = 0; i < 2; i++) {
            int idx = tid + i * 256;        // 0..511
            int kk = idx >> 5;              // 0..15
            int c = (idx & 31) * 4;
            *(float4*)&Bs[kk][c] = *(const float4*)&B[(size_t)(k0 + kk) * 128 + c];
        }
        __syncthreads();
        #pragma unroll
        for (int kk = 0; kk < 16; kk++) {
            float4 p0 = *(float4*)&As[kk][ty * 8];
            float4 p1 = *(float4*)&As[kk][ty * 8 + 4];
            float4 q0 = *(float4*)&Bs[kk][tx * 8];
            float4 q1 = *(float4*)&Bs[kk][tx * 8 + 4];
            float av[8] = {p0.x,p0.y,p0.z,p0.w,p1.x,p1.y,p1.z,p1.w};
            float bv[8] = {q0.x,q0.y,q0.z,q0.w,q1.x,q1.y,q1.z,q1.w};
            #pragma unroll
            for (int i = 0; i < 8; i++)
                #pragma unroll
                for (int j = 0; j < 8; j++) acc[i][j] += av[i] * bv[j];
        }
        __syncthreads();
    }
}

__device__ __forceinline__ void mm_epilogue(float* __restrict__ C,
                                            const float* __restrict__ bias,
                                            int row0, int M, float acc[8][8],
                                            int do_relu) {
    int tid = threadIdx.x;
    int tx = tid & 15, ty = tid >> 4;
    #pragma unroll
    for (int i = 0; i < 8; i++) {
        int gr = row0 + ty * 8 + i;
        if (gr >= M) continue;
        #pragma unroll
        for (int j = 0; j < 8; j++) {
            int c = tx * 8 + j;
            float vv = acc[i][j] + bias[c];
            if (do_relu) vv = fmaxf(vv, 0.f);
            C[(size_t)gr * 128 + c] = vv;
        }
    }
}

// h = relu(agg @ W_stack + x @ root + bias)
__global__ void __launch_bounds__(256)
gemm_h_kernel(const float* __restrict__ x,
              const float* __restrict__ W,      // [1024,128]
              const float* __restrict__ root,   // [128,128]
              const float* __restrict__ bias) {
    __shared__ float As[16][128];
    __shared__ float Bs[16][128];
    float acc[8][8];
    #pragma unroll
    for (int i = 0; i < 8; i++)
        #pragma unroll
        for (int j = 0; j < 8; j++) acc[i][j] = 0.f;
    int row0 = blockIdx.x * 128;
    mm_seg(g_agg, KAGG, KAGG, W, As, Bs, row0, NN, acc);
    mm_seg(x, GG, GG, root, As, Bs, row0, NN, acc);
    mm_epilogue(g_h, bias, row0, NN, acc, 1);
}

// q/k/v/skip in one launch: blockIdx.y selects the matrix
__global__ void __launch_bounds__(256)
gemm_qkvs_kernel(const float* __restrict__ Wq, const float* __restrict__ bq,
                 const float* __restrict__ Wk, const float* __restrict__ bk,
                 const float* __restrict__ Wv, const float* __restrict__ bv,
                 const float* __restrict__ Ws, const float* __restrict__ bs,
                 float* __restrict__ out) {
    const float* B; const float* bias; float* C;
    switch (blockIdx.y) {
        case 0:  B = Wq; bias = bq; C = g_q; break;
        case 1:  B = Wk; bias = bk; C = g_k; break;
        case 2:  B = Wv; bias = bv; C = g_v; break;
        default: B = Ws; bias = bs; C = out; break;
    }
    __shared__ float As[16][128];
    __shared__ float Bs[16][128];
    float acc[8][8];
    #pragma unroll
    for (int i = 0; i < 8; i++)
        #pragma unroll
        for (int j = 0; j < 8; j++) acc[i][j] = 0.f;
    int row0 = blockIdx.x * 128;
    mm_seg(g_h, H1, H1, B, As, Bs, row0, NN, acc);
    mm_epilogue(C, bias, row0, NN, acc, 0);
}

// ---------------- fused score + exp + denominator ---------------------------
// No max-subtraction: |score| ~ O(6) << 88, exp cannot overflow, and
// alpha = e/sum(e) is mathematically identical to the max-shifted form.
__global__ void score_exp_kernel(const int* __restrict__ src,
                                 const int* __restrict__ dst) {
    int e = blockIdx.x * 8 + (threadIdx.x >> 5);
    if (e >= EE) return;
    int lane = threadIdx.x & 31;
    int s = src[e], d = dst[e];
    float4 qv = *(const float4*)&g_q[(size_t)d * H2 + lane * 4];
    float4 kv = *(const float4*)&g_k[(size_t)s * H2 + lane * 4];
    float acc = qv.x * kv.x + qv.y * kv.y + qv.z * kv.z + qv.w * kv.w;
    #pragma unroll
    for (int o = 16; o; o >>= 1) acc += __shfl_xor_sync(0xFFFFFFFFu, acc, o);
    if (lane == 0) {
        float ex = __expf(acc * 0.08838834764831845f);  // 1/sqrt(128)
        g_e[e] = ex;
        atomicAdd(&g_den[d], ex);
    }
}

// ---------------- weighted V scatter ----------------------------------------
__global__ void scatter_v_kernel(const int* __restrict__ src,
                                 const int* __restrict__ dst,
                                 float* __restrict__ out) {
    int e = blockIdx.x * 8 + (threadIdx.x >> 5);
    if (e >= EE) return;
    int lane = threadIdx.x & 31;
    int s = src[e], d = dst[e];
    float alpha = g_e[e] / fmaxf(g_den[d], 1e-16f);
    float4 vv = *(const float4*)&g_v[(size_t)s * H2 + lane * 4];
    float* od = out + (size_t)d * H2 + lane * 4;
    atomicAdd(od + 0, alpha * vv.x);
    atomicAdd(od + 1, alpha * vv.y);
    atomicAdd(od + 2, alpha * vv.z);
    atomicAdd(od + 3, alpha * vv.w);
}

// ---------------- final relu in place ---------------------------------------
__global__ void relu_kernel(float* __restrict__ out, int n) {
    int i = blockIdx.x * blockDim.x + threadIdx.x;
    if (i < n) out[i] = fmaxf(out[i], 0.f);
}

// ---------------------------------------------------------------------------
extern "C" void kernel_launch(void* const* d_in, const int* in_sizes, int n_in,
                              void* d_out, int out_size) {
    const float* x        = (const float*)d_in[0];
    const int* edge_index = (const int*)d_in[1];   // [2, E]: src then dst
    const int* etype      = (const int*)d_in[2];
    const float* rgcn_w   = (const float*)d_in[3]; // [R, G, H1] == [1024,128]
    const float* rgcn_root= (const float*)d_in[4];
    const float* rgcn_b   = (const float*)d_in[5];
    const float* Wq = (const float*)d_in[6];  const float* bq = (const float*)d_in[7];
    const float* Wk = (const float*)d_in[8];  const float* bk = (const float*)d_in[9];
    const float* Wv = (const float*)d_in[10]; const float* bv = (const float*)d_in[11];
    const float* Ws = (const float*)d_in[12]; const float* bs = (const float*)d_in[13];
    float* out = (float*)d_out;

    const int* src = edge_index;
    const int* dst = edge_index + EE;

    // launch 0: zero everything (g_agg via float4 + cnt + den)
    {
        size_t n4 = ((size_t)NN * KAGG + 3) / 4;
        zero_kernel<<<(int)((n4 + 255) / 256), 256>>>();
    }
    // launch 1: per-(dst,rel) counts
    count_kernel<<<(EE + 255) / 256, 256>>>(dst, etype);
    // launch 2: RGCN scatter
    scatter_rgcn_kernel<<<(EE + 7) / 8, 256>>>(src, dst, etype, x);
    // launch 3 (ncu capture slot): big GEMM
    gemm_h_kernel<<<(NN + 127) / 128, 256>>>(x, rgcn_w, rgcn_root, rgcn_b);
    // launch 4: q,k,v,skip in one grid
    dim3 gq((NN + 127) / 128, 4);
    gemm_qkvs_kernel<<<gq, 256>>>(Wq, bq, Wk, bk, Wv, bv, Ws, bs, out);
    // launch 5: fused score+exp+den
    score_exp_kernel<<<(EE + 7) / 8, 256>>>(src, dst);
    // launch 6: alpha*v scatter onto skip
    scatter_v_kernel<<<(EE + 7) / 8, 256>>>(src, dst, out);
    // launch 7: final relu
    relu_kernel<<<(NN * H2 + 255) / 256, 256>>>(out, NN * H2);
}